// round 1
// baseline (speedup 1.0000x reference)
#include <cuda_runtime.h>
#include <cuda_bf16.h>

// y[b,c,h,w] = coef[c] * g[b,c,h,w]
// g: (32, 512, 64, 64) fp32, coef: (512,) fp32.
// H*W = 4096 contiguous floats per channel -> every float4 is channel-pure.
// float4-per-channel count = 1024 (2^10), channels = 512 (2^9):
//   c = (i4 >> 10) & 511   (no division)

__global__ __launch_bounds__(256)
void Gradient_28733331210651_kernel(const float4* __restrict__ g4,
                                    const float* __restrict__ coef,
                                    float4* __restrict__ out4,
                                    long long n4) {
    long long i4 = (long long)blockIdx.x * blockDim.x + threadIdx.x;
    if (i4 >= n4) return;
    int c = (int)((i4 >> 10) & 511);
    float s = __ldg(coef + c);
    float4 v = g4[i4];
    v.x *= s; v.y *= s; v.z *= s; v.w *= s;
    out4[i4] = v;
}

extern "C" void kernel_launch(void* const* d_in, const int* in_sizes, int n_in,
                              void* d_out, int out_size) {
    const float4* g4   = (const float4*)d_in[0];
    const float*  coef = (const float*)d_in[1];
    float4*       out4 = (float4*)d_out;

    long long n  = (long long)in_sizes[0];   // 32*512*64*64 = 67108864
    long long n4 = n >> 2;                   // 16777216

    const int threads = 256;
    long long blocks = (n4 + threads - 1) / threads;
    Gradient_28733331210651_kernel<<<(unsigned)blocks, threads>>>(g4, coef, out4, n4);
}

// round 4
// speedup vs baseline: 1.0090x; 1.0090x over previous
#include <cuda_runtime.h>
#include <cuda_bf16.h>

// y[b,c,h,w] = coef[c] * g[b,c,h,w]
// g: (32, 512, 64, 64) fp32, coef: (512,) fp32.
//
// Layout exploit: one block = 256 threads x 4 float4 = 4096 floats = exactly
// one (b,c) channel plane. So coef index is block-uniform: c = blockIdx.x & 511.
// Grid = 32*512 = 16384 blocks.
//
// ILP=4: 4 front-batched LDG.128 per thread (raises MLP / outstanding DRAM
// requests), then 4 FMUL groups, then 4 STG.128.
// Streaming hints (__ldcs/__stcs): zero-reuse 512 MiB stream through 126 MB
// L2 -> evict-first to cut L2 write-allocate/thrash pressure.

__global__ __launch_bounds__(256)
void Gradient_28733331210651_kernel(const float4* __restrict__ g4,
                                    const float* __restrict__ coef,
                                    float4* __restrict__ out4) {
    // Block-uniform channel + scale
    const int c = blockIdx.x & 511;
    const float s = __ldg(coef + c);

    const long long base = (long long)blockIdx.x * 1024 + threadIdx.x;

    // Front-batched loads (MLP=4)
    float4 v0 = __ldcs(g4 + base);
    float4 v1 = __ldcs(g4 + base + 256);
    float4 v2 = __ldcs(g4 + base + 512);
    float4 v3 = __ldcs(g4 + base + 768);

    v0.x *= s; v0.y *= s; v0.z *= s; v0.w *= s;
    v1.x *= s; v1.y *= s; v1.z *= s; v1.w *= s;
    v2.x *= s; v2.y *= s; v2.z *= s; v2.w *= s;
    v3.x *= s; v3.y *= s; v3.z *= s; v3.w *= s;

    __stcs(out4 + base,       v0);
    __stcs(out4 + base + 256, v1);
    __stcs(out4 + base + 512, v2);
    __stcs(out4 + base + 768, v3);
}

extern "C" void kernel_launch(void* const* d_in, const int* in_sizes, int n_in,
                              void* d_out, int out_size) {
    const float4* g4   = (const float4*)d_in[0];
    const float*  coef = (const float*)d_in[1];
    float4*       out4 = (float4*)d_out;

    // 32*512*64*64 floats; one block per 4096-float channel plane
    long long n  = (long long)in_sizes[0];      // 67108864
    long long blocks = n >> 12;                 // 16384

    Gradient_28733331210651_kernel<<<(unsigned)blocks, 256>>>(g4, coef, out4);
}